// round 1
// baseline (speedup 1.0000x reference)
#include <cuda_runtime.h>

#define CIN   32
#define FOUT  32
#define TH    8
#define TW    32
#define XROWS 10            // TH + 2 halo
#define XCOLS 36            // 34 used (TW + 2 halo), padded to 36 for float4 alignment
#define SW_FLOATS (9 * CIN * FOUT)          // 9216
#define SX_FLOATS (CIN * XROWS * XCOLS)     // 11520
#define SMEM_BYTES ((SW_FLOATS + SX_FLOATS) * 4)   // 82944 B
#define PARAM_STRIDE (SW_FLOATS + FOUT)     // 9248

__global__ __launch_bounds__(256, 2)
void conv3x3_per_batch_kernel(const float* __restrict__ x,
                              const float* __restrict__ params,
                              float* __restrict__ out) {
    extern __shared__ float smem[];
    float* sW = smem;               // [kh][kw][ci][f] flat = 9216 floats
    float* sX = smem + SW_FLOATS;   // [ci][XROWS][XCOLS]

    const int tid = threadIdx.x;
    const int bx = blockIdx.x;      // 0..3   (x tiles of 32)
    const int by = blockIdx.y;      // 0..15  (y tiles of 8)
    const int b  = blockIdx.z;      // batch
    const int x0 = bx * TW;
    const int y0 = by * TH;

    const float* p = params + (long)b * PARAM_STRIDE;

    // ---- load per-batch weights into smem (layout matches params exactly) ----
    #pragma unroll 4
    for (int i = tid; i < SW_FLOATS; i += 256) sW[i] = p[i];

    // ---- load haloed input tile, channel-major, zero-padded at image edges ----
    const float* xb = x + (long)b * 128 * 128 * CIN;
    for (int i = tid; i < 34 * XROWS * CIN; i += 256) {
        int ci  = i & 31;
        int pix = i >> 5;
        int r = pix / 34;
        int c = pix - r * 34;
        int gy = y0 + r - 1;
        int gx = x0 + c - 1;
        float v = 0.f;
        if ((unsigned)gy < 128u && (unsigned)gx < 128u)
            v = xb[(gy * 128 + gx) * CIN + ci];
        sX[(ci * XROWS + r) * XCOLS + c] = v;
    }
    __syncthreads();

    // ---- compute: thread = (output channel f, tile row) ----
    const int f   = tid & 31;
    const int row = tid >> 5;

    const float bias = p[SW_FLOATS + f];
    float acc[TW];
    #pragma unroll
    for (int i = 0; i < TW; i++) acc[i] = bias;

    #pragma unroll 1
    for (int kh = 0; kh < 3; kh++) {
        const float* sxrow = sX + (row + kh) * XCOLS;
        const float* swk   = sW + kh * 3 * CIN * FOUT + f;
        #pragma unroll 1
        for (int ci = 0; ci < CIN; ci++) {
            // broadcast (warp-uniform) float4 row load: 36 floats, 34 used
            float xr[36];
            const float4* src = (const float4*)(sxrow + ci * (XROWS * XCOLS));
            #pragma unroll
            for (int j = 0; j < 9; j++) {
                float4 v = src[j];
                xr[4*j + 0] = v.x; xr[4*j + 1] = v.y;
                xr[4*j + 2] = v.z; xr[4*j + 3] = v.w;
            }
            #pragma unroll
            for (int kw = 0; kw < 3; kw++) {
                float w = swk[kw * CIN * FOUT + ci * FOUT];   // lane-consecutive LDS
                #pragma unroll
                for (int pp = 0; pp < TW; pp++)
                    acc[pp] = fmaf(xr[pp + kw], w, acc[pp]);
            }
        }
    }

    // ---- store: warp writes 128B-coalesced (f = lane) ----
    float* ob = out + (((long)b * 128 + (y0 + row)) * 128 + x0) * FOUT + f;
    #pragma unroll
    for (int pp = 0; pp < TW; pp++) ob[pp * FOUT] = acc[pp];
}

extern "C" void kernel_launch(void* const* d_in, const int* in_sizes, int n_in,
                              void* d_out, int out_size) {
    const float* x      = (const float*)d_in[0];   // [32,128,128,32]
    const float* params = (const float*)d_in[1];   // [32,9248]
    float* out          = (float*)d_out;           // [32,128,128,32]

    cudaFuncSetAttribute(conv3x3_per_batch_kernel,
                         cudaFuncAttributeMaxDynamicSharedMemorySize, SMEM_BYTES);
    dim3 grid(4, 16, 32);
    conv3x3_per_batch_kernel<<<grid, 256, SMEM_BYTES>>>(x, params, out);
}

// round 3
// speedup vs baseline: 3.1590x; 3.1590x over previous
#include <cuda_runtime.h>
#include <cstdint>

#define WSIZE 9216
#define PSTRIDE 9248

// smem layout (uint32 words): X tile [4 rows][130 pix][32 ch], then W [288 k][32 f]
#define XT_WORDS (4 * 130 * 32)          // 16640
#define WT_WORDS (288 * 32)              // 9216
#define SMEM_BYTES ((XT_WORDS + WT_WORDS) * 4)   // 103424

__device__ __forceinline__ uint32_t tf32r(float f) {
    uint32_t r; asm("cvt.rna.tf32.f32 %0, %1;" : "=r"(r) : "f"(f)); return r;
}

__device__ __forceinline__ void mma_tf32(float& c0, float& c1, float& c2, float& c3,
                                         uint32_t a0, uint32_t a1, uint32_t a2, uint32_t a3,
                                         uint32_t b0, uint32_t b1) {
    asm volatile(
        "mma.sync.aligned.m16n8k8.row.col.f32.tf32.tf32.f32 "
        "{%0,%1,%2,%3}, {%4,%5,%6,%7}, {%8,%9}, {%0,%1,%2,%3};"
        : "+f"(c0), "+f"(c1), "+f"(c2), "+f"(c3)
        : "r"(a0), "r"(a1), "r"(a2), "r"(a3), "r"(b0), "r"(b1));
}

__global__ __launch_bounds__(256, 2)
void conv_mma(const float* __restrict__ x, const float* __restrict__ params,
              float* __restrict__ out) {
    extern __shared__ uint32_t smem[];
    uint32_t* sX = smem;              // [(row*130 + pix)*32 + (ci ^ ((pix&7)*4))]
    uint32_t* sW = smem + XT_WORDS;   // [k*32 + (f ^ ((k&3)*8))]

    const int tid = threadIdx.x;
    const int wid = tid >> 5;
    const int lid = tid & 31;
    const int g   = lid >> 2;         // group id 0..7
    const int t   = lid & 3;          // thread-in-group 0..3
    const int y2  = blockIdx.x;       // output row pair: rows 2*y2, 2*y2+1
    const int b   = blockIdx.y;

    // ---- build X tile: input rows 2*y2-1 .. 2*y2+2, pixels -1..128 (stored 0..129) ----
    const float* xb = x + (long)b * (128 * 128 * 32);
    #pragma unroll
    for (int it = 0; it < 16; it++) {
        int idx = tid + it * 256;            // 0..4095
        int c4  = idx & 7;                   // ci/4
        int px  = (idx >> 3) & 127;
        int row = idx >> 10;                 // 0..3
        int gy  = y2 * 2 + row - 1;
        int pix = px + 1;
        uint4 v = make_uint4(0u, 0u, 0u, 0u);
        if ((unsigned)gy < 128u) {
            float4 s = *(const float4*)(xb + ((gy * 128 + px) * 32 + c4 * 4));
            v.x = tf32r(s.x); v.y = tf32r(s.y); v.z = tf32r(s.z); v.w = tf32r(s.w);
        }
        *(uint4*)(sX + (row * 130 + pix) * 32 + ((c4 * 4) ^ ((pix & 7) * 4))) = v;
    }
    // zero pads at pix 0 and 129
    if (tid < 64) {
        int row  = tid >> 4;
        int side = (tid >> 3) & 1;
        int c4   = tid & 7;
        int pix  = side ? 129 : 0;
        *(uint4*)(sX + (row * 130 + pix) * 32 + ((c4 * 4) ^ ((pix & 7) * 4))) =
            make_uint4(0u, 0u, 0u, 0u);
    }

    // ---- build W tile: [k=kh*96+kw*32+ci][f], exactly params layout ----
    const float* pw = params + (long)b * PSTRIDE;
    #pragma unroll
    for (int it = 0; it < 9; it++) {
        int idx = tid + it * 256;            // 0..2303
        int k   = idx >> 3;
        int f4  = (idx & 7) * 4;
        float4 s = *(const float4*)(pw + k * 32 + f4);
        uint4 v;
        v.x = tf32r(s.x); v.y = tf32r(s.y); v.z = tf32r(s.z); v.w = tf32r(s.w);
        *(uint4*)(sW + k * 32 + (f4 ^ ((k & 3) * 8))) = v;
    }
    __syncthreads();

    // ---- warp assignment: yl = wid>>2 (local out row), m0 = (wid&3)*32 ----
    const int yl = wid >> 2;
    const int m0 = (wid & 3) * 32;

    float acc[2][4][4];
    #pragma unroll
    for (int mi = 0; mi < 2; mi++)
        #pragma unroll
        for (int nt = 0; nt < 4; nt++)
            #pragma unroll
            for (int j = 0; j < 4; j++) acc[mi][nt][j] = 0.f;

    #pragma unroll
    for (int kh = 0; kh < 3; kh++) {
        const uint32_t* xrow = sX + (yl + kh) * (130 * 32);
        #pragma unroll
        for (int kw = 0; kw < 3; kw++) {
            const int swz = ((g + kw) & 7) * 4;      // pix&7 == (g+kw)&7 (m0,mi*16 are mult of 8)
            #pragma unroll
            for (int c8 = 0; c8 < 4; c8++) {
                const int ci0 = c8 * 8;
                const int k0  = kh * 96 + kw * 32 + ci0;
                const int cA  = (ci0 + t) ^ swz;
                const int cA4 = (ci0 + t + 4) ^ swz;

                // B fragments for 4 n-tiles (shared across mi)
                uint32_t b0[4], b1[4];
                const uint32_t* wk0 = sW + (k0 + t) * 32;
                const uint32_t* wk4 = sW + (k0 + t + 4) * 32;
                #pragma unroll
                for (int nt = 0; nt < 4; nt++) {
                    int fc = (nt * 8 + g) ^ (t * 8);
                    b0[nt] = wk0[fc];
                    b1[nt] = wk4[fc];
                }

                #pragma unroll
                for (int mi = 0; mi < 2; mi++) {
                    const uint32_t* ap = xrow + (m0 + mi * 16 + g + kw) * 32;
                    uint32_t a0 = ap[cA];
                    uint32_t a1 = ap[8 * 32 + cA];
                    uint32_t a2 = ap[cA4];
                    uint32_t a3 = ap[8 * 32 + cA4];
                    #pragma unroll
                    for (int nt = 0; nt < 4; nt++)
                        mma_tf32(acc[mi][nt][0], acc[mi][nt][1],
                                 acc[mi][nt][2], acc[mi][nt][3],
                                 a0, a1, a2, a3, b0[nt], b1[nt]);
                }
            }
        }
    }

    // ---- epilogue: add bias, store ----
    const float* bp = pw + WSIZE;
    float* ob = out + (((long)(b * 128 + y2 * 2 + yl)) * 128) * 32;
    #pragma unroll
    for (int nt = 0; nt < 4; nt++) {
        int f = nt * 8 + t * 2;
        float2 bias = *(const float2*)(bp + f);
        #pragma unroll
        for (int mi = 0; mi < 2; mi++) {
            int px = m0 + mi * 16 + g;
            float2 o0, o1;
            o0.x = acc[mi][nt][0] + bias.x;
            o0.y = acc[mi][nt][1] + bias.y;
            o1.x = acc[mi][nt][2] + bias.x;
            o1.y = acc[mi][nt][3] + bias.y;
            *(float2*)(ob + px * 32 + f)       = o0;
            *(float2*)(ob + (px + 8) * 32 + f) = o1;
        }
    }
}

extern "C" void kernel_launch(void* const* d_in, const int* in_sizes, int n_in,
                              void* d_out, int out_size) {
    const float* x      = (const float*)d_in[0];   // [32,128,128,32]
    const float* params = (const float*)d_in[1];   // [32,9248]
    float* out          = (float*)d_out;           // [32,128,128,32]

    cudaFuncSetAttribute(conv_mma, cudaFuncAttributeMaxDynamicSharedMemorySize, SMEM_BYTES);
    dim3 grid(64, 32);   // (row-pair, batch)
    conv_mma<<<grid, 256, SMEM_BYTES>>>(x, params, out);
}

// round 4
// speedup vs baseline: 4.9032x; 1.5521x over previous
#include <cuda_runtime.h>
#include <cuda_fp16.h>
#include <cstdint>

#define WSIZE 9216
#define PSTRIDE 9248

#define XPITCH 20                       // 32-bit words per pixel (16 data + 4 pad; 20%32 pattern -> conflict-free)
#define XROWW  (130 * XPITCH)           // words per input row slice = 2600
#define XT_WORDS (6 * XROWW)            // 6 halo rows = 15600
#define WPITCH 148                      // words per filter f (144 data + 4 pad)
#define WT_WORDS (32 * WPITCH)          // 4736
#define SMEM_WORDS (XT_WORDS + WT_WORDS)
#define SMEM_BYTES (SMEM_WORDS * 4)     // 81344

__device__ __forceinline__ uint32_t pack2(float a, float b) {
    __half2 h = __floats2half2_rn(a, b);   // lo = a, hi = b
    return *(uint32_t*)&h;
}

__device__ __forceinline__ void mma_f16(float& c0, float& c1, float& c2, float& c3,
                                        uint32_t a0, uint32_t a1, uint32_t a2, uint32_t a3,
                                        uint32_t b0, uint32_t b1) {
    asm volatile(
        "mma.sync.aligned.m16n8k16.row.col.f32.f16.f16.f32 "
        "{%0,%1,%2,%3}, {%4,%5,%6,%7}, {%8,%9}, {%0,%1,%2,%3};"
        : "+f"(c0), "+f"(c1), "+f"(c2), "+f"(c3)
        : "r"(a0), "r"(a1), "r"(a2), "r"(a3), "r"(b0), "r"(b1));
}

__global__ __launch_bounds__(256, 2)
void conv_mma_f16(const float* __restrict__ x, const float* __restrict__ params,
                  float* __restrict__ out) {
    extern __shared__ uint32_t smem[];
    uint32_t* sX = smem;                 // [row][pix 0..129][XPITCH words]
    uint32_t* sW = smem + XT_WORDS;      // [f][WPITCH words], word w = fp16 pair (k=2w, 2w+1)

    const int tid = threadIdx.x;
    const int wid = tid >> 5;
    const int lid = tid & 31;
    const int g   = lid >> 2;            // 0..7
    const int t   = lid & 3;             // 0..3
    const int y0  = blockIdx.x * 4;      // 4 output rows per CTA
    const int b   = blockIdx.y;

    // ---- build X tile: input rows y0-1 .. y0+4, pixels -1..128 stored at 0..129, fp16 ----
    const float* xb = x + (long)b * (128 * 128 * 32);
    #pragma unroll
    for (int it = 0; it < 24; it++) {
        int idx = tid + it * 256;        // 0..6143
        int c4  = idx & 7;               // ci/4
        int px  = (idx >> 3) & 127;
        int row = idx >> 10;             // 0..5
        int gy  = y0 + row - 1;
        uint2 v = make_uint2(0u, 0u);
        if ((unsigned)gy < 128u) {
            float4 s = *(const float4*)(xb + ((gy * 128 + px) * 32 + c4 * 4));
            v.x = pack2(s.x, s.y);
            v.y = pack2(s.z, s.w);
        }
        *(uint2*)(sX + row * XROWW + (px + 1) * XPITCH + c4 * 2) = v;
    }
    // zero halo pads at pix 0 and 129
    if (tid < 192) {
        int row  = tid >> 5;             // 0..5
        int rem  = tid & 31;
        int pix  = (rem >> 4) ? 129 : 0;
        int w    = rem & 15;
        sX[row * XROWW + pix * XPITCH + w] = 0u;
    }

    // ---- build W tile transposed: sW[f][k] fp16, k = kh*96 + kw*32 + ci ----
    const float* pw = params + (long)b * PSTRIDE;
    __half* sWh = (__half*)sW;
    #pragma unroll
    for (int it = 0; it < 9; it++) {
        int idx = tid + it * 256;        // 0..2303
        int k   = idx >> 3;
        int f4  = (idx & 7) * 4;
        float4 s = *(const float4*)(pw + k * 32 + f4);
        sWh[(f4 + 0) * (2 * WPITCH) + k] = __float2half_rn(s.x);
        sWh[(f4 + 1) * (2 * WPITCH) + k] = __float2half_rn(s.y);
        sWh[(f4 + 2) * (2 * WPITCH) + k] = __float2half_rn(s.z);
        sWh[(f4 + 3) * (2 * WPITCH) + k] = __float2half_rn(s.w);
    }
    __syncthreads();

    // ---- warp tile: yl = local output row, m0 = pixel offset (64 px per warp) ----
    const int yl = wid >> 1;
    const int m0 = (wid & 1) * 64;

    float acc[4][4][4];
    #pragma unroll
    for (int mi = 0; mi < 4; mi++)
        #pragma unroll
        for (int nt = 0; nt < 4; nt++)
            #pragma unroll
            for (int j = 0; j < 4; j++) acc[mi][nt][j] = 0.f;

    #pragma unroll
    for (int kh = 0; kh < 3; kh++) {
        const uint32_t* xr = sX + (yl + kh) * XROWW;
        #pragma unroll
        for (int kw = 0; kw < 3; kw++) {
            #pragma unroll
            for (int c16 = 0; c16 < 2; c16++) {
                const int k0w = (kh * 96 + kw * 32 + c16 * 16) >> 1;   // word offset along k

                // B fragments (reused by all 4 mi)
                uint32_t b0[4], b1[4];
                const uint32_t* wp = sW + k0w + t;
                #pragma unroll
                for (int nt = 0; nt < 4; nt++) {
                    int f = nt * 8 + g;
                    b0[nt] = wp[f * WPITCH];
                    b1[nt] = wp[f * WPITCH + 4];
                }

                #pragma unroll
                for (int mi = 0; mi < 4; mi++) {
                    const uint32_t* ap = xr + (m0 + mi * 16 + g + kw) * XPITCH + c16 * 8 + t;
                    uint32_t a0 = ap[0];
                    uint32_t a1 = ap[8 * XPITCH];
                    uint32_t a2 = ap[4];
                    uint32_t a3 = ap[8 * XPITCH + 4];
                    #pragma unroll
                    for (int nt = 0; nt < 4; nt++)
                        mma_f16(acc[mi][nt][0], acc[mi][nt][1],
                                acc[mi][nt][2], acc[mi][nt][3],
                                a0, a1, a2, a3, b0[nt], b1[nt]);
                }
            }
        }
    }

    // ---- epilogue: + bias, store fp32 ----
    const float* bp = pw + WSIZE;
    float* ob = out + ((long)(b * 128 + y0 + yl)) * 128 * 32;
    #pragma unroll
    for (int nt = 0; nt < 4; nt++) {
        int f = nt * 8 + t * 2;
        float2 bias = *(const float2*)(bp + f);
        #pragma unroll
        for (int mi = 0; mi < 4; mi++) {
            int px = m0 + mi * 16 + g;
            float2 o0, o1;
            o0.x = acc[mi][nt][0] + bias.x;
            o0.y = acc[mi][nt][1] + bias.y;
            o1.x = acc[mi][nt][2] + bias.x;
            o1.y = acc[mi][nt][3] + bias.y;
            *(float2*)(ob + px * 32 + f)       = o0;
            *(float2*)(ob + (px + 8) * 32 + f) = o1;
        }
    }
}

extern "C" void kernel_launch(void* const* d_in, const int* in_sizes, int n_in,
                              void* d_out, int out_size) {
    const float* x      = (const float*)d_in[0];   // [32,128,128,32]
    const float* params = (const float*)d_in[1];   // [32,9248]
    float* out          = (float*)d_out;           // [32,128,128,32]

    cudaFuncSetAttribute(conv_mma_f16, cudaFuncAttributeMaxDynamicSharedMemorySize, SMEM_BYTES);
    dim3 grid(32, 32);   // (row-quad, batch)
    conv_mma_f16<<<grid, 256, SMEM_BYTES>>>(x, params, out);
}

// round 5
// speedup vs baseline: 5.3650x; 1.0942x over previous
#include <cuda_runtime.h>
#include <cuda_fp16.h>
#include <cstdint>

#define WSIZE 9216
#define PSTRIDE 9248

#define XPITCH 20                       // words per pixel (16 data + 4 pad); 20g%32 pattern -> conflict-free
#define XROWW  (130 * XPITCH)           // 2600
#define XT_WORDS (6 * XROWW)            // 15600
#define WPITCH 148                      // words per filter f (144 data + 4 pad)
#define WT_WORDS (32 * WPITCH)          // 4736
#define SMEM_BYTES ((XT_WORDS + WT_WORDS) * 4)   // 81344

// precomputed W^T in fp16, per batch: [f][WPITCH words], word w = (k=2w, 2w+1)
__device__ uint32_t gWT[32 * WT_WORDS];

__device__ __forceinline__ uint32_t pack2(float a, float b) {
    __half2 h = __floats2half2_rn(a, b);
    return *(uint32_t*)&h;
}

__device__ __forceinline__ void mma_f16(float& c0, float& c1, float& c2, float& c3,
                                        uint32_t a0, uint32_t a1, uint32_t a2, uint32_t a3,
                                        uint32_t b0, uint32_t b1) {
    asm volatile(
        "mma.sync.aligned.m16n8k16.row.col.f32.f16.f16.f32 "
        "{%0,%1,%2,%3}, {%4,%5,%6,%7}, {%8,%9}, {%0,%1,%2,%3};"
        : "+f"(c0), "+f"(c1), "+f"(c2), "+f"(c3)
        : "r"(a0), "r"(a1), "r"(a2), "r"(a3), "r"(b0), "r"(b1));
}

// ---- precompute: transpose + fp16-convert weights, once per batch ----
__global__ __launch_bounds__(256)
void wprep(const float* __restrict__ params) {
    __shared__ float s[288 * 33];
    const int b = blockIdx.x;
    const int tid = threadIdx.x;
    const float* pw = params + (long)b * PSTRIDE;
    #pragma unroll
    for (int i = tid; i < 9216; i += 256) {
        int k = i >> 5, f = i & 31;
        s[k * 33 + f] = pw[i];                 // coalesced LDG, conflict-free STS
    }
    __syncthreads();
    uint32_t* gw = gWT + b * WT_WORDS;
    #pragma unroll
    for (int i = tid; i < 32 * 144; i += 256) {
        int f = i / 144, w = i - f * 144;
        gw[f * WPITCH + w] = pack2(s[(2 * w) * 33 + f], s[(2 * w + 1) * 33 + f]);
    }
}

__global__ __launch_bounds__(256, 2)
void conv_mma_f16(const float* __restrict__ x, const float* __restrict__ params,
                  float* __restrict__ out) {
    extern __shared__ uint32_t smem[];
    uint32_t* sX = smem;                 // [row][pix 0..129][XPITCH]
    uint32_t* sW = smem + XT_WORDS;      // [f][WPITCH]

    const int tid = threadIdx.x;
    const int wid = tid >> 5;
    const int lid = tid & 31;
    const int g   = lid >> 2;
    const int t   = lid & 3;
    const int y0  = blockIdx.x * 4;
    const int b   = blockIdx.y;

    // ---- copy precomputed W^T tile (pure memcpy) ----
    const uint4* gw4 = (const uint4*)(gWT + b * WT_WORDS);
    #pragma unroll
    for (int it = 0; it < 5; it++) {
        int idx = tid + it * 256;
        if (idx < WT_WORDS / 4) ((uint4*)sW)[idx] = gw4[idx];
    }

    // ---- build X tile: rows y0-1 .. y0+4, pixels -1..128 at 0..129, fp16 ----
    const float* xb = x + (long)b * (128 * 128 * 32);
    #pragma unroll
    for (int it = 0; it < 24; it++) {
        int idx = tid + it * 256;
        int c4  = idx & 7;
        int px  = (idx >> 3) & 127;
        int row = idx >> 10;
        int gy  = y0 + row - 1;
        uint2 v = make_uint2(0u, 0u);
        if ((unsigned)gy < 128u) {
            float4 s = *(const float4*)(xb + ((gy * 128 + px) * 32 + c4 * 4));
            v.x = pack2(s.x, s.y);
            v.y = pack2(s.z, s.w);
        }
        *(uint2*)(sX + row * XROWW + (px + 1) * XPITCH + c4 * 2) = v;
    }
    if (tid < 192) {
        int row = tid >> 5, rem = tid & 31;
        int pix = (rem >> 4) ? 129 : 0;
        sX[row * XROWW + pix * XPITCH + (rem & 15)] = 0u;
    }
    __syncthreads();

    const int yl = wid >> 1;
    const int m0 = (wid & 1) * 64;

    float acc[4][4][4];
    #pragma unroll
    for (int mi = 0; mi < 4; mi++)
        #pragma unroll
        for (int nt = 0; nt < 4; nt++)
            #pragma unroll
            for (int j = 0; j < 4; j++) acc[mi][nt][j] = 0.f;

    #pragma unroll
    for (int kh = 0; kh < 3; kh++) {
        const uint32_t* xr = sX + (yl + kh) * XROWW;
        #pragma unroll
        for (int kw = 0; kw < 3; kw++) {
            #pragma unroll
            for (int c16 = 0; c16 < 2; c16++) {
                const int k0w = (kh * 96 + kw * 32 + c16 * 16) >> 1;

                uint32_t b0[4], b1[4];
                const uint32_t* wp = sW + k0w + t;
                #pragma unroll
                for (int nt = 0; nt < 4; nt++) {
                    int f = nt * 8 + g;
                    b0[nt] = wp[f * WPITCH];
                    b1[nt] = wp[f * WPITCH + 4];
                }

                #pragma unroll
                for (int mi = 0; mi < 4; mi++) {
                    const uint32_t* ap = xr + (m0 + mi * 16 + g + kw) * XPITCH + c16 * 8 + t;
                    uint32_t a0 = ap[0];
                    uint32_t a1 = ap[8 * XPITCH];
                    uint32_t a2 = ap[4];
                    uint32_t a3 = ap[8 * XPITCH + 4];
                    #pragma unroll
                    for (int nt = 0; nt < 4; nt++)
                        mma_f16(acc[mi][nt][0], acc[mi][nt][1],
                                acc[mi][nt][2], acc[mi][nt][3],
                                a0, a1, a2, a3, b0[nt], b1[nt]);
                }
            }
        }
    }

    // ---- epilogue: + bias, store ----
    const float* bp = params + (long)b * PSTRIDE + WSIZE;
    float* ob = out + ((long)(b * 128 + y0 + yl)) * 128 * 32;
    #pragma unroll
    for (int nt = 0; nt < 4; nt++) {
        int f = nt * 8 + t * 2;
        float2 bias = *(const float2*)(bp + f);
        #pragma unroll
        for (int mi = 0; mi < 4; mi++) {
            int px = m0 + mi * 16 + g;
            float2 o0, o1;
            o0.x = acc[mi][nt][0] + bias.x;
            o0.y = acc[mi][nt][1] + bias.y;
            o1.x = acc[mi][nt][2] + bias.x;
            o1.y = acc[mi][nt][3] + bias.y;
            *(float2*)(ob + px * 32 + f)       = o0;
            *(float2*)(ob + (px + 8) * 32 + f) = o1;
        }
    }
}

extern "C" void kernel_launch(void* const* d_in, const int* in_sizes, int n_in,
                              void* d_out, int out_size) {
    const float* x      = (const float*)d_in[0];
    const float* params = (const float*)d_in[1];
    float* out          = (float*)d_out;

    wprep<<<32, 256>>>(params);

    cudaFuncSetAttribute(conv_mma_f16, cudaFuncAttributeMaxDynamicSharedMemorySize, SMEM_BYTES);
    dim3 grid(32, 32);
    conv_mma_f16<<<grid, 256, SMEM_BYTES>>>(x, params, out);
}